// round 17
// baseline (speedup 1.0000x reference)
#include <cuda_runtime.h>

#define BB    8
#define NN    4096
#define CC    6
#define KNBR  16
#define H1    64
#define H2    128

static __device__ int    g_nbr[BB * NN * KNBR];         // 2 MB
static __device__ float  g_x1 [BB * NN * H1];           // 8 MB
static __device__ float4 g_pts[BB * NN];                // 512 KB : x,y,z,sq

#define FULLM 0xFFFFFFFFu

// packed f32x2 helpers (two independent rn-rounded fmas per instruction)
#define FMA2(d, a, b, c) \
    asm("fma.rn.f32x2 %0, %1, %2, %3;" : "=l"(d) : "l"(a), "l"(b), "l"(c))
#define SPLAT2(out, v) \
    asm("mov.b64 %0, {%1, %1};" : "=l"(out) : "r"(__float_as_uint(v)))
#define UNPACK2(lo, hi, in) \
    asm("mov.b64 {%0, %1}, %2;" : "=f"(lo), "=f"(hi) : "l"(in))

// ---------------------------------------------------------------------------
// Kernel 0: pack coords + squared norm (sq = (x*x + y*y) + z*z, per-op round).
// ---------------------------------------------------------------------------
__global__ void pack_kernel(const float* __restrict__ feats) {
    const int b = blockIdx.y;
    const int j = blockIdx.x * blockDim.x + threadIdx.x;
    const float* fj = feats + ((size_t)b * NN + j) * CC;
    float x = fj[0], y = fj[1], z = fj[2];
    float sq = __fadd_rn(__fadd_rn(__fmul_rn(x, x), __fmul_rn(y, y)),
                         __fmul_rn(z, z));
    g_pts[b * NN + j] = make_float4(x, y, z, sq);
}

// ---------------------------------------------------------------------------
// Kernel 1: exact KNN (k=16). Warp = 2 queries; top-17 lane-distributed
// (lanes 0..16 sorted ascending; lane 0 = self). d2 via query-side
// premultiplied -2 coords (<=1-ulp of reference; rank-16 gaps ~1e-3).
// Warm start: bitonic sort of block-0 candidates. Inserts: per-query loops,
// stable warp insertion; tau updated once per eventful block (filter only).
// ---------------------------------------------------------------------------
__device__ __forceinline__ float d2_eval(float m2x, float m2y, float m2z,
                                         float sqq, float4 p) {
    return __fmaf_rn(m2x, p.x,
           __fmaf_rn(m2y, p.y,
           __fmaf_rn(m2z, p.z, __fadd_rn(sqq, p.w))));
}

__global__ __launch_bounds__(512)
void knn_kernel() {
    const int lane = threadIdx.x & 31;
    const int wid  = threadIdx.x >> 5;                  // 16 warps
    const int b    = blockIdx.y;
    const int i0   = blockIdx.x * 32 + wid * 2;
    const int i1   = i0 + 1;
    const float4* pb = g_pts + b * NN;
    const float4 qa = __ldg(pb + i0);
    const float4 qb = __ldg(pb + i1);
    const float m2xa = qa.x * -2.0f, m2ya = qa.y * -2.0f, m2za = qa.z * -2.0f;
    const float m2xb = qb.x * -2.0f, m2yb = qb.y * -2.0f, m2zb = qb.z * -2.0f;

    // ---- warm start: bitonic sort of block-0's 32 candidates per query ----
    float bda, bdb;
    int   bia, bib;
    {
        float4 p = __ldg(pb + lane);
        bda = d2_eval(m2xa, m2ya, m2za, qa.w, p);
        bdb = d2_eval(m2xb, m2yb, m2zb, qb.w, p);
        bia = lane; bib = lane;

#pragma unroll
        for (int k = 2; k <= 32; k <<= 1) {
#pragma unroll
            for (int j = k >> 1; j > 0; j >>= 1) {
                bool takeSmall = ((lane & k) == 0) == ((lane & j) == 0);
                {
                    float od = __shfl_xor_sync(FULLM, bda, j);
                    int   oi = __shfl_xor_sync(FULLM, bia, j);
                    bool oLess = (od < bda) || (od == bda && oi < bia);
                    if (takeSmall == oLess) { bda = od; bia = oi; }
                }
                {
                    float od = __shfl_xor_sync(FULLM, bdb, j);
                    int   oi = __shfl_xor_sync(FULLM, bib, j);
                    bool oLess = (od < bdb) || (od == bdb && oi < bib);
                    if (takeSmall == oLess) { bdb = od; bib = oi; }
                }
            }
        }
    }
    float taua = __shfl_sync(FULLM, bda, 16);
    float taub = __shfl_sync(FULLM, bdb, 16);

    // ---- main scan ----
#pragma unroll 4
    for (int jb = 32; jb < NN; jb += 32) {
        const float4 p = __ldg(pb + jb + lane);
        float d2a = d2_eval(m2xa, m2ya, m2za, qa.w, p);
        float d2b = d2_eval(m2xb, m2yb, m2zb, qb.w, p);

        unsigned balA = __ballot_sync(FULLM, d2a < taua);
        unsigned balB = __ballot_sync(FULLM, d2b < taub);

        if (balA) {                                     // warp-uniform
            do {
                int src = __ffs(balA) - 1;
                balA &= balA - 1;
                float nd = __shfl_sync(FULLM, d2a, src);
                int   ni = jb + src;
                unsigned m = __ballot_sync(FULLM, nd < bda);
                float ud = __shfl_up_sync(FULLM, bda, 1);
                int   ui = __shfl_up_sync(FULLM, bia, 1);
                if (m) {
                    int pos = __ffs(m) - 1;
                    if (lane >= pos) { bda = (lane == pos) ? nd : ud;
                                       bia = (lane == pos) ? ni : ui; }
                }
            } while (balA);
            taua = __shfl_sync(FULLM, bda, 16);
        }

        if (balB) {
            do {
                int src = __ffs(balB) - 1;
                balB &= balB - 1;
                float nd = __shfl_sync(FULLM, d2b, src);
                int   ni = jb + src;
                unsigned m = __ballot_sync(FULLM, nd < bdb);
                float ud = __shfl_up_sync(FULLM, bdb, 1);
                int   ui = __shfl_up_sync(FULLM, bib, 1);
                if (m) {
                    int pos = __ffs(m) - 1;
                    if (lane >= pos) { bdb = (lane == pos) ? nd : ud;
                                       bib = (lane == pos) ? ni : ui; }
                }
            } while (balB);
            taub = __shfl_sync(FULLM, bdb, 16);
        }
    }

    if (lane >= 1 && lane < 17) {                       // lane 0 == self
        g_nbr[(b * NN + i0) * KNBR + lane - 1] = bia;
        g_nbr[(b * NN + i1) * KNBR + lane - 1] = bib;
    }
}

// ---------------------------------------------------------------------------
// Kernel 2: x1 = relu( ((sum_{j in nbr(i)} feats[j]) + feats[i]) @ W1 * inv + b1 )
// No feats smem staging: rows gathered via __ldg (feats is L2-resident).
// ---------------------------------------------------------------------------
__global__ __launch_bounds__(256)
void layer1_kernel(const float* __restrict__ feats,
                   const float* __restrict__ W1,
                   const float* __restrict__ b1) {
    __shared__ float W1s[CC * H1];
    __shared__ float b1s[H1];

    for (int t = threadIdx.x; t < CC * H1; t += blockDim.x) W1s[t] = W1[t];
    if (threadIdx.x < H1) b1s[threadIdx.x] = b1[threadIdx.x];
    __syncthreads();

    const int b = blockIdx.y;
    const int i = blockIdx.x * blockDim.x + threadIdx.x;
    const float* fb = feats + (size_t)b * NN * CC;

    float s[CC];
    {
        const float* fi = fb + (size_t)i * CC;
#pragma unroll
        for (int c = 0; c < CC; ++c) s[c] = __ldg(fi + c);
    }

    const int* nb = g_nbr + (size_t)(b * NN + i) * KNBR;
    int4 nidx[4];
#pragma unroll
    for (int q = 0; q < 4; ++q) nidx[q] = __ldg((const int4*)nb + q);

#pragma unroll
    for (int q = 0; q < 4; ++q) {
        int js[4] = {nidx[q].x, nidx[q].y, nidx[q].z, nidx[q].w};
#pragma unroll
        for (int u = 0; u < 4; ++u) {
            const float* fj = fb + (size_t)js[u] * CC;
#pragma unroll
            for (int c = 0; c < CC; ++c) s[c] += __ldg(fj + c);
        }
    }

    float* xo = g_x1 + (size_t)(b * NN + i) * H1;
    const float inv = 1.0f / 17.0f;
#pragma unroll 2
    for (int c4 = 0; c4 < H1; c4 += 4) {
        float r[4];
#pragma unroll
        for (int u = 0; u < 4; ++u) {
            int c = c4 + u;
            float a = s[0] * W1s[c];
#pragma unroll
            for (int kk = 1; kk < CC; ++kk) a = fmaf(s[kk], W1s[kk * H1 + c], a);
            r[u] = fmaxf(fmaf(a, inv, b1s[c]), 0.0f);
        }
        *(float4*)&xo[c4] = make_float4(r[0], r[1], r[2], r[3]);
    }
}

// ---------------------------------------------------------------------------
// Kernel 3 (fused): gather-sum x1 -> x2 = relu(.@W2*inv+b2) -> out = x2@Wf+bf
// Matmul phases use packed fma.rn.f32x2 (FFMA2): accumulators + weight rows
// as 64-bit pairs -> fma-pipe instruction count halves. Results bit-identical
// (each packed lane is an independent rn fma; per-column order unchanged).
// W2 in smem; Wf via __ldg (L1-resident) -> ~81KB smem -> 2 blocks/SM.
// ---------------------------------------------------------------------------
__device__ __forceinline__ float f4get(float4 v, int kk) {
    return kk == 0 ? v.x : kk == 1 ? v.y : kk == 2 ? v.z : v.w;
}

#define PTS 64

__global__ __launch_bounds__(512, 2)
void layer2_kernel(const float* __restrict__ W2,
                   const float* __restrict__ b2,
                   const float* __restrict__ Wf,
                   const float* __restrict__ bf,
                   float* __restrict__ out) {
    extern __shared__ float smem_f[];
    float* W2s = smem_f;                 // 64*128
    float* b2s = W2s + H1 * H2;          // 128
    float* bfs = b2s + H2;               // 128
    float* s1  = bfs + H2;               // PTS*64
    float* x2s = s1 + PTS * H1;          // PTS*128

    for (int t = threadIdx.x; t < H1 * H2; t += blockDim.x) W2s[t] = W2[t];
    if (threadIdx.x < H2) { b2s[threadIdx.x] = b2[threadIdx.x]; bfs[threadIdx.x] = bf[threadIdx.x]; }

    const int lane = threadIdx.x & 31;
    const int warp = threadIdx.x >> 5;              // 16 warps
    const int gp0  = blockIdx.x * PTS;
    const int b    = gp0 >> 12;
    const float* x1b = g_x1 + (size_t)b * NN * H1;

#pragma unroll
    for (int pp = 0; pp < 4; ++pp) {
        int p  = warp * 4 + pp;
        int gi = gp0 + p;
        int li = gi & (NN - 1);
        const int* nb = g_nbr + (size_t)gi * KNBR;
        float2 v = ((const float2*)(x1b + (size_t)li * H1))[lane];
        float a0 = v.x, a1 = v.y;
#pragma unroll
        for (int n = 0; n < KNBR; ++n) {
            int j = nb[n];
            float2 w = ((const float2*)(x1b + (size_t)j * H1))[lane];
            a0 += w.x; a1 += w.y;
        }
        ((float2*)(s1 + p * H1))[lane] = make_float2(a0, a1);
    }
    __syncthreads();

    const float inv = 1.0f / 17.0f;

    // phase 2: x2 = relu(s1 @ W2 * inv + b2); cols lane*4..lane*4+3 (FFMA2)
    {
        unsigned long long acc[4][2];
#pragma unroll
        for (int pp = 0; pp < 4; ++pp) { acc[pp][0] = 0ULL; acc[pp][1] = 0ULL; }

#pragma unroll 4
        for (int k = 0; k < H1; k += 4) {
            float4 xv[4];
#pragma unroll
            for (int pp = 0; pp < 4; ++pp)
                xv[pp] = *(const float4*)&s1[(warp * 4 + pp) * H1 + k];
#pragma unroll
            for (int kk = 0; kk < 4; ++kk) {
                double2 wd = *(const double2*)&W2s[(k + kk) * H2 + lane * 4];
                unsigned long long w0 = __double_as_longlong(wd.x);
                unsigned long long w1 = __double_as_longlong(wd.y);
#pragma unroll
                for (int pp = 0; pp < 4; ++pp) {
                    unsigned long long xp;
                    SPLAT2(xp, f4get(xv[pp], kk));
                    FMA2(acc[pp][0], xp, w0, acc[pp][0]);
                    FMA2(acc[pp][1], xp, w1, acc[pp][1]);
                }
            }
        }
#pragma unroll
        for (int pp = 0; pp < 4; ++pp) {
            float a0, a1, a2, a3;
            UNPACK2(a0, a1, acc[pp][0]);
            UNPACK2(a2, a3, acc[pp][1]);
            float4 r;
            r.x = fmaxf(fmaf(a0, inv, b2s[lane * 4 + 0]), 0.0f);
            r.y = fmaxf(fmaf(a1, inv, b2s[lane * 4 + 1]), 0.0f);
            r.z = fmaxf(fmaf(a2, inv, b2s[lane * 4 + 2]), 0.0f);
            r.w = fmaxf(fmaf(a3, inv, b2s[lane * 4 + 3]), 0.0f);
            *(float4*)&x2s[(warp * 4 + pp) * H2 + lane * 4] = r;
        }
    }
    __syncthreads();

    // phase 3: out = x2 @ Wf + bf  (Wf via __ldg; FFMA2)
    {
        unsigned long long acc[4][2];
#pragma unroll
        for (int pp = 0; pp < 4; ++pp) { acc[pp][0] = 0ULL; acc[pp][1] = 0ULL; }

#pragma unroll 4
        for (int k = 0; k < H2; k += 4) {
            float4 xv[4];
#pragma unroll
            for (int pp = 0; pp < 4; ++pp)
                xv[pp] = *(const float4*)&x2s[(warp * 4 + pp) * H2 + k];
#pragma unroll
            for (int kk = 0; kk < 4; ++kk) {
                double2 wd = __ldg((const double2*)&Wf[(k + kk) * H2 + lane * 4]);
                unsigned long long w0 = __double_as_longlong(wd.x);
                unsigned long long w1 = __double_as_longlong(wd.y);
#pragma unroll
                for (int pp = 0; pp < 4; ++pp) {
                    unsigned long long xp;
                    SPLAT2(xp, f4get(xv[pp], kk));
                    FMA2(acc[pp][0], xp, w0, acc[pp][0]);
                    FMA2(acc[pp][1], xp, w1, acc[pp][1]);
                }
            }
        }
#pragma unroll
        for (int pp = 0; pp < 4; ++pp) {
            int gi = gp0 + warp * 4 + pp;
            float a0, a1, a2, a3;
            UNPACK2(a0, a1, acc[pp][0]);
            UNPACK2(a2, a3, acc[pp][1]);
            float4 r;
            r.x = a0 + bfs[lane * 4 + 0];
            r.y = a1 + bfs[lane * 4 + 1];
            r.z = a2 + bfs[lane * 4 + 2];
            r.w = a3 + bfs[lane * 4 + 3];
            *(float4*)&out[(size_t)gi * H2 + lane * 4] = r;
        }
    }
}

// ---------------------------------------------------------------------------
extern "C" void kernel_launch(void* const* d_in, const int* in_sizes, int n_in,
                              void* d_out, int out_size) {
    const float* feats = (const float*)d_in[0];
    const float* W1    = (const float*)d_in[1];
    const float* b1    = (const float*)d_in[2];
    const float* W2    = (const float*)d_in[3];
    const float* b2    = (const float*)d_in[4];
    const float* Wf    = (const float*)d_in[5];
    const float* bf    = (const float*)d_in[6];
    float* out = (float*)d_out;

    const int smem_l2  = (H1 * H2 + 2 * H2 + PTS * H1 + PTS * H2)
                         * (int)sizeof(float);                           // ~81 KB

    cudaFuncSetAttribute(layer2_kernel, cudaFuncAttributeMaxDynamicSharedMemorySize, smem_l2);

    dim3 gPK(NN / 256, BB);
    pack_kernel<<<gPK, 256>>>(feats);
    dim3 gKNN(NN / 32, BB);                       // 2 queries/warp, 16 warps/block
    knn_kernel<<<gKNN, 512>>>();
    dim3 gL1(NN / 256, BB);
    layer1_kernel<<<gL1, 256>>>(feats, W1, b1);
    layer2_kernel<<<(BB * NN) / PTS, 512, smem_l2>>>(W2, b2, Wf, bf, out);
}